// round 16
// baseline (speedup 1.0000x reference)
#include <cuda_runtime.h>

#define IN_DIM 256
#define FEAT   33152      // 256 + (256 + 256*256)/2 = 259 * 128
#define NB     8          // batch
#define NROWS  8192       // NHEAD * S * D_MODEL
#define KITERS (FEAT / 128)   // 259, exact
#define OUTF   64

typedef unsigned long long u64;

// scratch (allocation-free rule: __device__ globals)
__device__ __align__(16) float g_feats[NB * FEAT];
__device__ __align__(16) float g_head[NB * NROWS];

// packed dual-FMA: d.lo = a.lo*b.lo + c.lo ; d.hi = a.hi*b.hi + c.hi
__device__ __forceinline__ u64 ffma2(u64 a, u64 b, u64 c) {
    u64 d;
    asm("fma.rn.f32x2 %0, %1, %2, %3;" : "=l"(d) : "l"(a), "l"(b), "l"(c));
    return d;
}

__device__ __forceinline__ float sum2(u64 v) {
    union { u64 u; float f[2]; } cvt;
    cvt.u = v;
    return cvt.f[0] + cvt.f[1];
}

// streaming (evict-first) 16B load for the 1-GB W stream
__device__ __forceinline__ ulonglong2 ldcs128(const void* p) {
    ulonglong2 v;
    asm volatile("ld.global.cs.v2.u64 {%0, %1}, [%2];"
                 : "=l"(v.x), "=l"(v.y) : "l"(p));
    return v;
}

// default-cached (L1-resident) 16B load for feats
__device__ __forceinline__ ulonglong2 ldca128(const void* p) {
    ulonglong2 v;
    asm("ld.global.ca.v2.u64 {%0, %1}, [%2];"
        : "=l"(v.x), "=l"(v.y) : "l"(p));
    return v;
}

// ---------------------------------------------------------------------------
// Kernel A: build feats = [x_flat | triu(x x^T)] for all 8 batches.
// ---------------------------------------------------------------------------
__global__ void build_feats_kernel(const float* __restrict__ x) {
    __shared__ float xs[NB][IN_DIM];
    int tid = threadIdx.x;                       // 256 threads
    for (int t = tid; t < NB * IN_DIM; t += 256)
        xs[t >> 8][t & 255] = x[t];
    __syncthreads();

    int i = blockIdx.x;
    if (i < IN_DIM) {
        int j = tid;
        if (j >= i) {
            int off = IN_DIM + i * IN_DIM - (i * (i - 1)) / 2 + (j - i);
            #pragma unroll
            for (int b = 0; b < NB; b++)
                g_feats[b * FEAT + off] = xs[b][i] * xs[b][j];
        }
    } else {
        int j = tid;
        #pragma unroll
        for (int b = 0; b < NB; b++)
            g_feats[b * FEAT + j] = xs[b][j];
    }
}

// ---------------------------------------------------------------------------
// Kernel B: head_out[b][r] = dot(feats[b], W[r]) + bh[r]
//   High-coverage variant: warp = 2 rows x 8 batches -> 4096 warps total,
//   24 warps/SM (vs 16 in the R=4 baseline) for +50% latency coverage.
//   Sync-free, smem-free; W streamed .cs, feats via L1 .ca; FFMA2 accs.
//   1024 blocks x 128 thr (4 warps x 2 rows = 8 rows/block).
// ---------------------------------------------------------------------------
__global__ void __launch_bounds__(128, 6)
head_gemm_kernel(const float* __restrict__ W, const float* __restrict__ bh) {
    int warp = threadIdx.x >> 5;                 // 0..3
    int lane = threadIdx.x & 31;
    int row0 = blockIdx.x * 8 + warp * 2;

    const float* w0 = W + (size_t)row0 * FEAT + lane * 4;
    const float* w1 = w0 + FEAT;
    const float* fb = g_feats + lane * 4;

    u64 acc[2][8];
    #pragma unroll
    for (int r = 0; r < 2; r++)
        #pragma unroll
        for (int b = 0; b < 8; b++) acc[r][b] = 0ull;

    #pragma unroll 2
    for (int it = 0; it < KITERS; it++) {
        int k = it * 128;
        ulonglong2 a0 = ldcs128(w0 + k);
        ulonglong2 a1 = ldcs128(w1 + k);
        #pragma unroll
        for (int b = 0; b < 8; b++) {
            ulonglong2 f = ldca128(fb + b * FEAT + k);
            acc[0][b] = ffma2(a0.x, f.x, acc[0][b]);
            acc[0][b] = ffma2(a0.y, f.y, acc[0][b]);
            acc[1][b] = ffma2(a1.x, f.x, acc[1][b]);
            acc[1][b] = ffma2(a1.y, f.y, acc[1][b]);
        }
    }

    // per-(row,batch): fold k-parity halves, warp-reduce, write
    #pragma unroll
    for (int r = 0; r < 2; r++) {
        #pragma unroll
        for (int b = 0; b < 8; b++) {
            float v = sum2(acc[r][b]);
            #pragma unroll
            for (int o = 16; o > 0; o >>= 1)
                v += __shfl_xor_sync(0xffffffffu, v, o);
            if (lane == 0)
                g_head[b * NROWS + row0 + r] = v + bh[row0 + r];
        }
    }
}

// ---------------------------------------------------------------------------
// Kernel C: out[b][s][o] = dot(concat[b][s], W_out[o]) + b_out[o]
// ---------------------------------------------------------------------------
__global__ void out_gemm_kernel(const float* __restrict__ Wout,
                                const float* __restrict__ bout,
                                float* __restrict__ out) {
    __shared__ float cs[256];
    int bs = blockIdx.x;
    int b  = bs >> 5;
    int s  = bs & 31;
    int t  = threadIdx.x;    // 64 threads

    #pragma unroll
    for (int q = 0; q < 4; q++) {
        int j = t + q * 64;
        cs[j] = g_head[b * NROWS + (j >> 6) * 2048 + s * 64 + (j & 63)];
    }
    __syncthreads();

    const float* wr = Wout + t * 256;
    float sum = bout[t];
    #pragma unroll
    for (int j = 0; j < 256; j += 4) {
        float4 w = *(const float4*)(wr + j);
        sum = fmaf(w.x, cs[j],
              fmaf(w.y, cs[j + 1],
              fmaf(w.z, cs[j + 2],
              fmaf(w.w, cs[j + 3], sum))));
    }
    out[bs * 64 + t] = sum;
}

// ---------------------------------------------------------------------------
extern "C" void kernel_launch(void* const* d_in, const int* in_sizes, int n_in,
                              void* d_out, int out_size) {
    const float* x   = (const float*)d_in[0];   // (8,32,8)
    const float* W   = (const float*)d_in[1];   // (4,2048,33152)
    const float* bh  = (const float*)d_in[2];   // (4,2048)
    const float* Wo  = (const float*)d_in[3];   // (64,256)
    const float* bo  = (const float*)d_in[4];   // (64,)
    float* out = (float*)d_out;                 // (8,32,64)

    build_feats_kernel<<<IN_DIM + 1, 256>>>(x);
    head_gemm_kernel<<<NROWS / 8, 128>>>(W, bh);
    out_gemm_kernel<<<256, 64>>>(Wo, bo, out);
}

// round 17
// speedup vs baseline: 1.6394x; 1.6394x over previous
#include <cuda_runtime.h>

#define IN_DIM 256
#define FEAT   33152      // 256 + (256 + 256*256)/2 = 259 * 128
#define NB     8          // batch
#define NROWS  8192       // NHEAD * S * D_MODEL
#define KITERS (FEAT / 128)   // 259, exact
#define OUTF   64

typedef unsigned long long u64;

// scratch (allocation-free rule: __device__ globals)
__device__ __align__(16) float g_feats[NB * FEAT];
__device__ __align__(16) float g_head[NB * NROWS];

// packed dual-FMA: d.lo = a.lo*b.lo + c.lo ; d.hi = a.hi*b.hi + c.hi
__device__ __forceinline__ u64 ffma2(u64 a, u64 b, u64 c) {
    u64 d;
    asm("fma.rn.f32x2 %0, %1, %2, %3;" : "=l"(d) : "l"(a), "l"(b), "l"(c));
    return d;
}

__device__ __forceinline__ float sum2(u64 v) {
    union { u64 u; float f[2]; } cvt;
    cvt.u = v;
    return cvt.f[0] + cvt.f[1];
}

// streaming (evict-first) 16B load for the 1-GB W stream
__device__ __forceinline__ ulonglong2 ldcs128(const void* p) {
    ulonglong2 v;
    asm volatile("ld.global.cs.v2.u64 {%0, %1}, [%2];"
                 : "=l"(v.x), "=l"(v.y) : "l"(p));
    return v;
}

// default-cached (L1-resident) 16B load for feats
__device__ __forceinline__ ulonglong2 ldca128(const void* p) {
    ulonglong2 v;
    asm("ld.global.ca.v2.u64 {%0, %1}, [%2];"
        : "=l"(v.x), "=l"(v.y) : "l"(p));
    return v;
}

// ---------------------------------------------------------------------------
// Kernel A: build feats = [x_flat | triu(x x^T)] for all 8 batches.
// ---------------------------------------------------------------------------
__global__ void build_feats_kernel(const float* __restrict__ x) {
    __shared__ float xs[NB][IN_DIM];
    int tid = threadIdx.x;                       // 256 threads
    for (int t = tid; t < NB * IN_DIM; t += 256)
        xs[t >> 8][t & 255] = x[t];
    __syncthreads();

    int i = blockIdx.x;
    if (i < IN_DIM) {
        int j = tid;
        if (j >= i) {
            int off = IN_DIM + i * IN_DIM - (i * (i - 1)) / 2 + (j - i);
            #pragma unroll
            for (int b = 0; b < NB; b++)
                g_feats[b * FEAT + off] = xs[b][i] * xs[b][j];
        }
    } else {
        int j = tid;
        #pragma unroll
        for (int b = 0; b < NB; b++)
            g_feats[b * FEAT + j] = xs[b][j];
    }
}

// ---------------------------------------------------------------------------
// Kernel B: head_out[b][r] = dot(feats[b], W[r]) + bh[r]
//   Sync-free: no shared memory, no barriers. feats served from L1 (.ca,
//   shared working window across all warps on the SM); W streamed .cs.
//   1024 blocks x 64 threads; each warp owns 4 rows; lane covers k%128/4.
// ---------------------------------------------------------------------------
__global__ void __launch_bounds__(64, 8)
head_gemm_kernel(const float* __restrict__ W, const float* __restrict__ bh) {
    int warp = threadIdx.x >> 5;                 // 0..1
    int lane = threadIdx.x & 31;
    int row0 = blockIdx.x * 8 + warp * 4;

    const float* w0 = W + (size_t)row0 * FEAT + lane * 4;
    const float* w1 = w0 + FEAT;
    const float* w2 = w1 + FEAT;
    const float* w3 = w2 + FEAT;
    const float* fb = g_feats + lane * 4;

    u64 acc[4][8];
    #pragma unroll
    for (int r = 0; r < 4; r++)
        #pragma unroll
        for (int b = 0; b < 8; b++) acc[r][b] = 0ull;

    #pragma unroll 2
    for (int it = 0; it < KITERS; it++) {
        int k = it * 128;
        ulonglong2 a0 = ldcs128(w0 + k);
        ulonglong2 a1 = ldcs128(w1 + k);
        ulonglong2 a2 = ldcs128(w2 + k);
        ulonglong2 a3 = ldcs128(w3 + k);
        #pragma unroll
        for (int b = 0; b < 8; b++) {
            ulonglong2 f = ldca128(fb + b * FEAT + k);
            acc[0][b] = ffma2(a0.x, f.x, acc[0][b]);
            acc[0][b] = ffma2(a0.y, f.y, acc[0][b]);
            acc[1][b] = ffma2(a1.x, f.x, acc[1][b]);
            acc[1][b] = ffma2(a1.y, f.y, acc[1][b]);
            acc[2][b] = ffma2(a2.x, f.x, acc[2][b]);
            acc[2][b] = ffma2(a2.y, f.y, acc[2][b]);
            acc[3][b] = ffma2(a3.x, f.x, acc[3][b]);
            acc[3][b] = ffma2(a3.y, f.y, acc[3][b]);
        }
    }

    // per-(row,batch): fold k-parity halves, warp-reduce, write
    #pragma unroll
    for (int r = 0; r < 4; r++) {
        #pragma unroll
        for (int b = 0; b < 8; b++) {
            float v = sum2(acc[r][b]);
            #pragma unroll
            for (int o = 16; o > 0; o >>= 1)
                v += __shfl_xor_sync(0xffffffffu, v, o);
            if (lane == 0)
                g_head[b * NROWS + row0 + r] = v + bh[row0 + r];
        }
    }
}

// ---------------------------------------------------------------------------
// Kernel C: out[b][s][o] = dot(concat[b][s], W_out[o]) + b_out[o]
// ---------------------------------------------------------------------------
__global__ void out_gemm_kernel(const float* __restrict__ Wout,
                                const float* __restrict__ bout,
                                float* __restrict__ out) {
    __shared__ float cs[256];
    int bs = blockIdx.x;
    int b  = bs >> 5;
    int s  = bs & 31;
    int t  = threadIdx.x;    // 64 threads

    #pragma unroll
    for (int q = 0; q < 4; q++) {
        int j = t + q * 64;
        cs[j] = g_head[b * NROWS + (j >> 6) * 2048 + s * 64 + (j & 63)];
    }
    __syncthreads();

    const float* wr = Wout + t * 256;
    float sum = bout[t];
    #pragma unroll
    for (int j = 0; j < 256; j += 4) {
        float4 w = *(const float4*)(wr + j);
        sum = fmaf(w.x, cs[j],
              fmaf(w.y, cs[j + 1],
              fmaf(w.z, cs[j + 2],
              fmaf(w.w, cs[j + 3], sum))));
    }
    out[bs * 64 + t] = sum;
}

// ---------------------------------------------------------------------------
extern "C" void kernel_launch(void* const* d_in, const int* in_sizes, int n_in,
                              void* d_out, int out_size) {
    const float* x   = (const float*)d_in[0];   // (8,32,8)
    const float* W   = (const float*)d_in[1];   // (4,2048,33152)
    const float* bh  = (const float*)d_in[2];   // (4,2048)
    const float* Wo  = (const float*)d_in[3];   // (64,256)
    const float* bo  = (const float*)d_in[4];   // (64,)
    float* out = (float*)d_out;                 // (8,32,64)

    build_feats_kernel<<<IN_DIM + 1, 256>>>(x);
    head_gemm_kernel<<<NROWS / 8, 64>>>(W, bh);
    out_gemm_kernel<<<256, 64>>>(Wo, bo, out);
}